// round 3
// baseline (speedup 1.0000x reference)
#include <cuda_runtime.h>
#include <math_constants.h>

// FullAttention: out[b,l,h,d] = softmax_s( (1/8) * Q[b,l,h,:]·K[b,s,h,:] ) @ V[b,s,h,:]
// B=4, L=S=2048, H=8, E=D=64, fp32.
//
// Design: flash-attention, one CTA per (b, h, 64-query tile). 256 threads,
// each owns a 4x4 micro-tile of the 64x64 score tile (16x16 thread grid).
// Q/K tiles stored e-major (transposed) in smem so both GEMMs read two
// float4s per inner iteration -> 16 FFMA per 2 LDS.128 (FMA-pipe bound).

namespace {

constexpr int Bv = 4, Lv = 2048, Sv = 2048, Hv = 8, Ev = 64, Dv = 64;
constexpr int BQ = 64;   // queries per CTA
constexpr int BS = 64;   // keys per inner tile
constexpr int QK_STRIDE = 68;  // padded (17*4B banks shift), 16B-aligned rows
constexpr int VP_STRIDE = 68;

struct SmemLayout {
    float Qs[Ev][QK_STRIDE];   // Qs[e][row]   (transposed, pre-scaled)
    float Ks[Ev][QK_STRIDE];   // Ks[e][col]   (transposed)
    float Vs[BS][VP_STRIDE];   // Vs[s][d]
    float Ps[BS][VP_STRIDE];   // Ps[s][row]   (softmax probs, transposed)
};

__global__ void __launch_bounds__(256, 2)
fullattn_kernel(const float* __restrict__ Qg,
                const float* __restrict__ Kg,
                const float* __restrict__ Vg,
                float* __restrict__ Og)
{
    extern __shared__ char smem_raw[];
    SmemLayout& sm = *reinterpret_cast<SmemLayout*>(smem_raw);

    const int tid = threadIdx.x;
    const int tx  = tid & 15;   // score-tile column group (also lane bits 0..3)
    const int ty  = tid >> 4;   // score-tile row group
    const int b   = blockIdx.z;
    const int h   = blockIdx.y;
    const int q0  = blockIdx.x * BQ;

    // ---- Load Q tile once: transposed + pre-scaled by 1/sqrt(E) ----
    {
        const int r  = tid >> 2;         // 0..63 query row within tile
        const int e0 = (tid & 3) * 16;   // 0/16/32/48
        const float* src = Qg + (((size_t)b * Lv + (q0 + r)) * Hv + h) * Ev + e0;
        const float scale = 0.125f;      // 1/sqrt(64)
        #pragma unroll
        for (int k = 0; k < 4; k++) {
            float4 v = *reinterpret_cast<const float4*>(src + 4 * k);
            sm.Qs[e0 + 4*k + 0][r] = v.x * scale;
            sm.Qs[e0 + 4*k + 1][r] = v.y * scale;
            sm.Qs[e0 + 4*k + 2][r] = v.z * scale;
            sm.Qs[e0 + 4*k + 3][r] = v.w * scale;
        }
    }

    float  m[4], lsum[4];
    float4 acc[4];
    #pragma unroll
    for (int i = 0; i < 4; i++) {
        m[i] = -CUDART_INF_F;
        lsum[i] = 0.0f;
        acc[i] = make_float4(0.f, 0.f, 0.f, 0.f);
    }

    for (int s0 = 0; s0 < Sv; s0 += BS) {
        __syncthreads();  // previous PV finished before Ks/Vs/Ps overwrite

        // ---- Load K (transposed) and V (direct) tiles ----
        {
            const int r  = tid >> 2;         // key row within tile
            const int c0 = (tid & 3) * 16;
            const float* ksrc = Kg + (((size_t)b * Sv + (s0 + r)) * Hv + h) * Ev + c0;
            const float* vsrc = Vg + (((size_t)b * Sv + (s0 + r)) * Hv + h) * Dv + c0;
            #pragma unroll
            for (int k = 0; k < 4; k++) {
                float4 kv = *reinterpret_cast<const float4*>(ksrc + 4 * k);
                sm.Ks[c0 + 4*k + 0][r] = kv.x;
                sm.Ks[c0 + 4*k + 1][r] = kv.y;
                sm.Ks[c0 + 4*k + 2][r] = kv.z;
                sm.Ks[c0 + 4*k + 3][r] = kv.w;
                float4 vv = *reinterpret_cast<const float4*>(vsrc + 4 * k);
                *reinterpret_cast<float4*>(&sm.Vs[r][c0 + 4*k]) = vv;
            }
        }
        __syncthreads();

        // ---- QK^T: 4x4 micro-tile, rows ty*4+i, cols tx*4+j ----
        float sc[4][4];
        #pragma unroll
        for (int i = 0; i < 4; i++)
            #pragma unroll
            for (int j = 0; j < 4; j++) sc[i][j] = 0.0f;

        #pragma unroll 8
        for (int e = 0; e < Ev; e++) {
            float4 a  = *reinterpret_cast<const float4*>(&sm.Qs[e][ty * 4]);
            float4 bb = *reinterpret_cast<const float4*>(&sm.Ks[e][tx * 4]);
            float av[4] = {a.x, a.y, a.z, a.w};
            float bv[4] = {bb.x, bb.y, bb.z, bb.w};
            #pragma unroll
            for (int i = 0; i < 4; i++)
                #pragma unroll
                for (int j = 0; j < 4; j++)
                    sc[i][j] = fmaf(av[i], bv[j], sc[i][j]);
        }

        // ---- Online softmax (row reductions across tx = lane bits 0..3) ----
        #pragma unroll
        for (int i = 0; i < 4; i++) {
            float tmax = fmaxf(fmaxf(sc[i][0], sc[i][1]), fmaxf(sc[i][2], sc[i][3]));
            #pragma unroll
            for (int w = 1; w < 16; w <<= 1)
                tmax = fmaxf(tmax, __shfl_xor_sync(0xffffffffu, tmax, w));

            float mnew  = fmaxf(m[i], tmax);
            float alpha = __expf(m[i] - mnew);   // exp(-inf)=0 on first tile
            float psum  = 0.0f;
            #pragma unroll
            for (int j = 0; j < 4; j++) {
                float p = __expf(sc[i][j] - mnew);
                sc[i][j] = p;
                psum += p;
            }
            #pragma unroll
            for (int w = 1; w < 16; w <<= 1)
                psum += __shfl_xor_sync(0xffffffffu, psum, w);

            lsum[i] = lsum[i] * alpha + psum;
            m[i]    = mnew;
            acc[i].x *= alpha; acc[i].y *= alpha;
            acc[i].z *= alpha; acc[i].w *= alpha;
        }

        // ---- Stage P transposed: Ps[s][row] ----
        #pragma unroll
        for (int i = 0; i < 4; i++)
            #pragma unroll
            for (int j = 0; j < 4; j++)
                sm.Ps[tx * 4 + j][ty * 4 + i] = sc[i][j];
        __syncthreads();

        // ---- PV: acc[row i][d j] += P[s][row] * V[s][d] ----
        #pragma unroll 8
        for (int ss = 0; ss < BS; ss++) {
            float4 a  = *reinterpret_cast<const float4*>(&sm.Ps[ss][ty * 4]);
            float4 vv = *reinterpret_cast<const float4*>(&sm.Vs[ss][tx * 4]);
            float av[4] = {a.x, a.y, a.z, a.w};
            #pragma unroll
            for (int i = 0; i < 4; i++) {
                acc[i].x = fmaf(av[i], vv.x, acc[i].x);
                acc[i].y = fmaf(av[i], vv.y, acc[i].y);
                acc[i].z = fmaf(av[i], vv.z, acc[i].z);
                acc[i].w = fmaf(av[i], vv.w, acc[i].w);
            }
        }
    }

    // ---- Epilogue: O = acc / l, coalesced float4 stores ----
    #pragma unroll
    for (int i = 0; i < 4; i++) {
        float inv = 1.0f / lsum[i];
        float4 o = make_float4(acc[i].x * inv, acc[i].y * inv,
                               acc[i].z * inv, acc[i].w * inv);
        float* dst = Og + (((size_t)b * Lv + (q0 + ty * 4 + i)) * Hv + h) * Dv + tx * 4;
        *reinterpret_cast<float4*>(dst) = o;
    }
}

}  // namespace

extern "C" void kernel_launch(void* const* d_in, const int* in_sizes, int n_in,
                              void* d_out, int out_size)
{
    const float* Q = (const float*)d_in[0];
    const float* K = (const float*)d_in[1];
    const float* V = (const float*)d_in[2];
    float* O = (float*)d_out;

    cudaFuncSetAttribute(fullattn_kernel,
                         cudaFuncAttributeMaxDynamicSharedMemorySize,
                         (int)sizeof(SmemLayout));

    dim3 grid(Lv / BQ, Hv, Bv);
    fullattn_kernel<<<grid, 256, sizeof(SmemLayout)>>>(Q, K, V, O);
}

// round 12
// speedup vs baseline: 3.3820x; 3.3820x over previous
#include <cuda_runtime.h>
#include <cuda_bf16.h>
#include <math_constants.h>
#include <cstdint>

// FullAttention B=4 H=8 L=S=2048 E=D=64 fp32.
// mma.sync m16n8k16 bf16 split-precision (3 passes per GEMM), FA2-style.

namespace {

constexpr int Bv = 4, Lv = 2048, Sv = 2048, Hv = 8, Ev = 64, Dv = 64;
constexpr int BQ = 128;          // q rows per CTA
constexpr int BS = 64;           // keys per tile
constexpr int NT = Sv / BS;      // 32
constexpr size_t NELEM = (size_t)Bv * Lv * Hv * Ev;  // 4194304

// split-bf16 scratch (static device memory: allowed)
__device__ __nv_bfloat16 g_Qh[NELEM], g_Ql[NELEM];
__device__ __nv_bfloat16 g_Kh[NELEM], g_Kl[NELEM];
__device__ __nv_bfloat16 g_Vh[NELEM], g_Vl[NELEM];

// smem map (per CTA): two 32KB KV stages + persistent Q (hi16K + lo16K)
constexpr uint32_t STAGE_SZ = 32768;           // KH 8K | KL 8K | VH 8K | VL 8K
constexpr uint32_t QOFF     = 65536;           // QH 16K | QL 16K
constexpr uint32_t SMEM_TOTAL = 98304 + 1024;  // + align slack

__device__ __forceinline__ uint32_t packbf(float x0, float x1) {  // lo=x0, hi=x1
    uint32_t r;
    asm("cvt.rn.bf16x2.f32 %0, %1, %2;" : "=r"(r) : "f"(x1), "f"(x0));
    return r;
}
__device__ __forceinline__ float bflo(uint32_t r) { return __int_as_float(r << 16); }
__device__ __forceinline__ float bfhi(uint32_t r) { return __int_as_float(r & 0xffff0000u); }

__device__ __forceinline__ uint32_t smem_u32(const void* p) {
    uint32_t a;
    asm("{ .reg .u64 t; cvta.to.shared.u64 t, %1; cvt.u32.u64 %0, t; }"
        : "=r"(a) : "l"(p));
    return a;
}
__device__ __forceinline__ uint32_t swz(uint32_t x) { return x ^ ((x >> 3) & 0x70); }

__device__ __forceinline__ void cpa16(uint32_t dst, const void* src) {
    asm volatile("cp.async.cg.shared.global [%0], [%1], 16;" :: "r"(dst), "l"(src));
}
__device__ __forceinline__ void cp_commit() { asm volatile("cp.async.commit_group;"); }
template <int N>
__device__ __forceinline__ void cp_wait() {
    asm volatile("cp.async.wait_group %0;" :: "n"(N));
}

__device__ __forceinline__ void ldsm_x4(uint32_t a, uint32_t* r) {
    asm volatile("ldmatrix.sync.aligned.m8n8.x4.shared.b16 {%0,%1,%2,%3}, [%4];"
                 : "=r"(r[0]), "=r"(r[1]), "=r"(r[2]), "=r"(r[3]) : "r"(a));
}
__device__ __forceinline__ void ldsm_x2(uint32_t a, uint32_t* r) {
    asm volatile("ldmatrix.sync.aligned.m8n8.x2.shared.b16 {%0,%1}, [%2];"
                 : "=r"(r[0]), "=r"(r[1]) : "r"(a));
}
__device__ __forceinline__ void ldsm_x2t(uint32_t a, uint32_t* r) {
    asm volatile("ldmatrix.sync.aligned.m8n8.x2.trans.shared.b16 {%0,%1}, [%2];"
                 : "=r"(r[0]), "=r"(r[1]) : "r"(a));
}
__device__ __forceinline__ void mma16816(float* c, const uint32_t* a, const uint32_t* b) {
    asm volatile(
        "mma.sync.aligned.m16n8k16.row.col.f32.bf16.bf16.f32 "
        "{%0,%1,%2,%3}, {%4,%5,%6,%7}, {%8,%9}, {%0,%1,%2,%3};"
        : "+f"(c[0]), "+f"(c[1]), "+f"(c[2]), "+f"(c[3])
        : "r"(a[0]), "r"(a[1]), "r"(a[2]), "r"(a[3]), "r"(b[0]), "r"(b[1]));
}

// ---- preprocess: fp32 -> (hi, lo) bf16 split; Q pre-scaled by 1/8 ----
__global__ void pre_kernel(const float* __restrict__ Q, const float* __restrict__ K,
                           const float* __restrict__ V)
{
    uint32_t i4 = blockIdx.x * blockDim.x + threadIdx.x;  // float4 index
    const float4* src;
    __nv_bfloat16 *dh, *dl;
    float s = 1.0f;
    if (blockIdx.y == 0)      { src = (const float4*)Q; dh = g_Qh; dl = g_Ql; s = 0.125f; }
    else if (blockIdx.y == 1) { src = (const float4*)K; dh = g_Kh; dl = g_Kl; }
    else                      { src = (const float4*)V; dh = g_Vh; dl = g_Vl; }
    float4 v = src[i4];
    float x0 = v.x * s, x1 = v.y * s, x2 = v.z * s, x3 = v.w * s;
    uint32_t h01 = packbf(x0, x1), h23 = packbf(x2, x3);
    uint32_t l01 = packbf(x0 - bflo(h01), x1 - bfhi(h01));
    uint32_t l23 = packbf(x2 - bflo(h23), x3 - bfhi(h23));
    ((uint2*)dh)[i4] = make_uint2(h01, h23);
    ((uint2*)dl)[i4] = make_uint2(l01, l23);
}

// ---- main attention kernel ----
__global__ void __launch_bounds__(256, 2)
attn_kernel(float* __restrict__ Og)
{
    extern __shared__ char smraw[];
    const uint32_t sb = (smem_u32(smraw) + 1023u) & ~1023u;

    const int tid = threadIdx.x, lane = tid & 31, w = tid >> 5;
    const int b = blockIdx.z, h = blockIdx.y, q0 = blockIdx.x * BQ;

    // per-lane ldmatrix constants
    const uint32_t rowK = lane & 7;
    const uint32_t selK = ((lane >> 3) & 1) * 16;
    const uint32_t rA   = 16 * w + (lane & 7) + ((lane >> 3) & 1) * 8;
    const uint32_t cA   = ((uint32_t)lane >> 4) * 16;
    const uint32_t rowV = lane & 15;

    // ---- prologue: Q chunks (16/thread) + tile0 as group0; tile1 as group1 ----
#pragma unroll
    for (int c = 0; c < 16; c++) {
        uint32_t id = c * 256 + tid;               // 0..4095
        uint32_t half = id >> 11, r = (id >> 3) & 127, c16 = id & 7;
        const __nv_bfloat16* src =
            (half ? g_Ql : g_Qh) + (((size_t)b * Lv + q0 + r) * Hv + h) * Ev + c16 * 8;
        cpa16(sb + QOFF + half * 16384 + swz(r * 128 + c16 * 16), src);
    }
    auto issue = [&](int t, uint32_t stage) {
#pragma unroll
        for (int c = 0; c < 8; c++) {
            uint32_t id = c * 256 + tid;           // 0..2047
            uint32_t half = id >> 9;               // 0:KH 1:KL 2:VH 3:VL
            uint32_t r = (id >> 3) & 63, c16 = id & 7;
            const __nv_bfloat16* base =
                half == 0 ? g_Kh : half == 1 ? g_Kl : half == 2 ? g_Vh : g_Vl;
            const __nv_bfloat16* src =
                base + (((size_t)b * Sv + t * BS + r) * Hv + h) * Ev + c16 * 8;
            cpa16(sb + stage + half * 8192 + swz(r * 128 + c16 * 16), src);
        }
    };
    issue(0, 0);
    cp_commit();           // group0 = Q + tile0
    issue(1, STAGE_SZ);
    cp_commit();           // group1 = tile1

    float Oacc[32];
#pragma unroll
    for (int i = 0; i < 32; i++) Oacc[i] = 0.0f;
    float m0 = -CUDART_INF_F, m1 = -CUDART_INF_F, l0 = 0.0f, l1 = 0.0f;

    for (int t = 0; t < NT; t++) {
        if (t == NT - 1) cp_wait<0>(); else cp_wait<1>();
        __syncthreads();
        const uint32_t stg = sb + (uint32_t)(t & 1) * STAGE_SZ;
        const uint32_t kh = stg, kl = stg + 8192, vh = stg + 16384, vl = stg + 24576;

        // ---- QK^T: S(16x64 per warp) = Qh*Kh + Ql*Kh + Qh*Kl ----
        float sc[32];
#pragma unroll
        for (int i = 0; i < 32; i++) sc[i] = 0.0f;
#pragma unroll
        for (int ks = 0; ks < 4; ks++) {
            uint32_t aH[4], aL[4];
            const uint32_t qa = sb + QOFF + swz(rA * 128 + ks * 32 + cA);
            ldsm_x4(qa, aH);
            ldsm_x4(qa + 16384, aL);
            const uint32_t kboff = swz(rowK * 128 + ks * 32 + selK);
#pragma unroll
            for (int j = 0; j < 8; j++) {
                uint32_t bh[2], bl[2];
                ldsm_x2(kh + j * 1024 + kboff, bh);
                ldsm_x2(kl + j * 1024 + kboff, bl);
                mma16816(sc + 4 * j, aH, bh);
                mma16816(sc + 4 * j, aL, bh);
                mma16816(sc + 4 * j, aH, bl);
            }
        }

        // ---- online softmax (rows g and g+8; quad = lanes tig 0..3) ----
        float mx0 = -CUDART_INF_F, mx1 = -CUDART_INF_F;
#pragma unroll
        for (int j = 0; j < 8; j++) {
            mx0 = fmaxf(mx0, fmaxf(sc[4 * j], sc[4 * j + 1]));
            mx1 = fmaxf(mx1, fmaxf(sc[4 * j + 2], sc[4 * j + 3]));
        }
#pragma unroll
        for (int d = 1; d < 4; d <<= 1) {
            mx0 = fmaxf(mx0, __shfl_xor_sync(0xffffffffu, mx0, d));
            mx1 = fmaxf(mx1, __shfl_xor_sync(0xffffffffu, mx1, d));
        }
        const float mn0 = fmaxf(m0, mx0), mn1 = fmaxf(m1, mx1);
        const float al0 = __expf(m0 - mn0), al1 = __expf(m1 - mn1);
        m0 = mn0; m1 = mn1;
        float s0 = 0.0f, s1 = 0.0f;
#pragma unroll
        for (int j = 0; j < 8; j++) {
            sc[4 * j]     = __expf(sc[4 * j]     - mn0);
            sc[4 * j + 1] = __expf(sc[4 * j + 1] - mn0);
            s0 += sc[4 * j] + sc[4 * j + 1];
            sc[4 * j + 2] = __expf(sc[4 * j + 2] - mn1);
            sc[4 * j + 3] = __expf(sc[4 * j + 3] - mn1);
            s1 += sc[4 * j + 2] + sc[4 * j + 3];
        }
#pragma unroll
        for (int d = 1; d < 4; d <<= 1) {
            s0 += __shfl_xor_sync(0xffffffffu, s0, d);
            s1 += __shfl_xor_sync(0xffffffffu, s1, d);
        }
        l0 = l0 * al0 + s0;
        l1 = l1 * al1 + s1;
#pragma unroll
        for (int j = 0; j < 8; j++) {
            Oacc[4 * j]     *= al0;
            Oacc[4 * j + 1] *= al0;
            Oacc[4 * j + 2] *= al1;
            Oacc[4 * j + 3] *= al1;
        }

        // ---- PV: O += Ph*Vh + Pl*Vh + Ph*Vl  (P from C-layout regs) ----
#pragma unroll
        for (int ks = 0; ks < 4; ks++) {
            uint32_t pH[4], pL[4];
#pragma unroll
            for (int u = 0; u < 4; u++) {
                float x0 = sc[8 * ks + 2 * u], x1 = sc[8 * ks + 2 * u + 1];
                uint32_t hp = packbf(x0, x1);
                pH[u] = hp;
                pL[u] = packbf(x0 - bflo(hp), x1 - bfhi(hp));
            }
#pragma unroll
            for (int j = 0; j < 8; j++) {
                uint32_t bh[2], bl[2];
                const uint32_t va = swz((16 * ks + rowV) * 128 + j * 16);
                ldsm_x2t(vh + va, bh);
                ldsm_x2t(vl + va, bl);
                mma16816(Oacc + 4 * j, pH, bh);
                mma16816(Oacc + 4 * j, pL, bh);
                mma16816(Oacc + 4 * j, pH, bl);
            }
        }

        __syncthreads();  // all warps done with stage (t&1)
        if (t + 2 < NT) {
            issue(t + 2, (uint32_t)(t & 1) * STAGE_SZ);
            cp_commit();
        }
    }

    // ---- epilogue ----
    const float inv0 = 1.0f / l0, inv1 = 1.0f / l1;
    const int r0 = q0 + 16 * w + (lane >> 2);
    const size_t base0 = (((size_t)b * Lv + r0) * Hv + h) * Dv;
    const size_t base1 = base0 + (size_t)8 * Hv * Dv;
#pragma unroll
    for (int j = 0; j < 8; j++) {
        const int col = 8 * j + 2 * (lane & 3);
        float2 o0 = make_float2(Oacc[4 * j] * inv0, Oacc[4 * j + 1] * inv0);
        float2 o1 = make_float2(Oacc[4 * j + 2] * inv1, Oacc[4 * j + 3] * inv1);
        *reinterpret_cast<float2*>(Og + base0 + col) = o0;
        *reinterpret_cast<float2*>(Og + base1 + col) = o1;
    }
}

}  // namespace

extern "C" void kernel_launch(void* const* d_in, const int* in_sizes, int n_in,
                              void* d_out, int out_size)
{
    const float* Q = (const float*)d_in[0];
    const float* K = (const float*)d_in[1];
    const float* V = (const float*)d_in[2];
    float* O = (float*)d_out;

    // split/scale preprocess: 4M float4-quads per tensor / 256 = 4096 blocks
    pre_kernel<<<dim3((unsigned)(NELEM / 4 / 256), 3, 1), 256>>>(Q, K, V);

    cudaFuncSetAttribute(attn_kernel,
                         cudaFuncAttributeMaxDynamicSharedMemorySize,
                         (int)SMEM_TOTAL);
    attn_kernel<<<dim3(Lv / BQ, Hv, Bv), 256, SMEM_TOTAL>>>(O);
}

// round 13
// speedup vs baseline: 3.3827x; 1.0002x over previous
#include <cuda_runtime.h>
#include <cuda_bf16.h>
#include <math_constants.h>
#include <cstdint>

// FullAttention B=4 H=8 L=S=2048 E=D=64 fp32.
// mma.sync m16n8k16 bf16 split-precision (3 passes per GEMM), FA2-style.

namespace {

constexpr int Bv = 4, Lv = 2048, Sv = 2048, Hv = 8, Ev = 64, Dv = 64;
constexpr int BQ = 128;          // q rows per CTA
constexpr int BS = 64;           // keys per tile
constexpr int NT = Sv / BS;      // 32
constexpr size_t NELEM = (size_t)Bv * Lv * Hv * Ev;  // 4194304

// split-bf16 scratch (static device memory: allowed)
__device__ __nv_bfloat16 g_Qh[NELEM], g_Ql[NELEM];
__device__ __nv_bfloat16 g_Kh[NELEM], g_Kl[NELEM];
__device__ __nv_bfloat16 g_Vh[NELEM], g_Vl[NELEM];

// smem map (per CTA): two 32KB KV stages + persistent Q (hi16K + lo16K)
constexpr uint32_t STAGE_SZ = 32768;           // KH 8K | KL 8K | VH 8K | VL 8K
constexpr uint32_t QOFF     = 65536;           // QH 16K | QL 16K
constexpr uint32_t SMEM_TOTAL = 98304 + 1024;  // + align slack

__device__ __forceinline__ uint32_t packbf(float x0, float x1) {  // lo=x0, hi=x1
    uint32_t r;
    asm("cvt.rn.bf16x2.f32 %0, %1, %2;" : "=r"(r) : "f"(x1), "f"(x0));
    return r;
}
__device__ __forceinline__ float bflo(uint32_t r) { return __int_as_float(r << 16); }
__device__ __forceinline__ float bfhi(uint32_t r) { return __int_as_float(r & 0xffff0000u); }

__device__ __forceinline__ uint32_t smem_u32(const void* p) {
    uint32_t a;
    asm("{ .reg .u64 t; cvta.to.shared.u64 t, %1; cvt.u32.u64 %0, t; }"
        : "=r"(a) : "l"(p));
    return a;
}
__device__ __forceinline__ uint32_t swz(uint32_t x) { return x ^ ((x >> 3) & 0x70); }

__device__ __forceinline__ void cpa16(uint32_t dst, const void* src) {
    asm volatile("cp.async.cg.shared.global [%0], [%1], 16;" :: "r"(dst), "l"(src));
}
__device__ __forceinline__ void cp_commit() { asm volatile("cp.async.commit_group;"); }
template <int N>
__device__ __forceinline__ void cp_wait() {
    asm volatile("cp.async.wait_group %0;" :: "n"(N));
}

__device__ __forceinline__ void ldsm_x4(uint32_t a, uint32_t* r) {
    asm volatile("ldmatrix.sync.aligned.m8n8.x4.shared.b16 {%0,%1,%2,%3}, [%4];"
                 : "=r"(r[0]), "=r"(r[1]), "=r"(r[2]), "=r"(r[3]) : "r"(a));
}
__device__ __forceinline__ void ldsm_x2(uint32_t a, uint32_t* r) {
    asm volatile("ldmatrix.sync.aligned.m8n8.x2.shared.b16 {%0,%1}, [%2];"
                 : "=r"(r[0]), "=r"(r[1]) : "r"(a));
}
__device__ __forceinline__ void ldsm_x2t(uint32_t a, uint32_t* r) {
    asm volatile("ldmatrix.sync.aligned.m8n8.x2.trans.shared.b16 {%0,%1}, [%2];"
                 : "=r"(r[0]), "=r"(r[1]) : "r"(a));
}
__device__ __forceinline__ void mma16816(float* c, const uint32_t* a, const uint32_t* b) {
    asm volatile(
        "mma.sync.aligned.m16n8k16.row.col.f32.bf16.bf16.f32 "
        "{%0,%1,%2,%3}, {%4,%5,%6,%7}, {%8,%9}, {%0,%1,%2,%3};"
        : "+f"(c[0]), "+f"(c[1]), "+f"(c[2]), "+f"(c[3])
        : "r"(a[0]), "r"(a[1]), "r"(a[2]), "r"(a[3]), "r"(b[0]), "r"(b[1]));
}

// ---- preprocess: fp32 -> (hi, lo) bf16 split; Q pre-scaled by 1/8 ----
__global__ void pre_kernel(const float* __restrict__ Q, const float* __restrict__ K,
                           const float* __restrict__ V)
{
    uint32_t i4 = blockIdx.x * blockDim.x + threadIdx.x;  // float4 index
    const float4* src;
    __nv_bfloat16 *dh, *dl;
    float s = 1.0f;
    if (blockIdx.y == 0)      { src = (const float4*)Q; dh = g_Qh; dl = g_Ql; s = 0.125f; }
    else if (blockIdx.y == 1) { src = (const float4*)K; dh = g_Kh; dl = g_Kl; }
    else                      { src = (const float4*)V; dh = g_Vh; dl = g_Vl; }
    float4 v = src[i4];
    float x0 = v.x * s, x1 = v.y * s, x2 = v.z * s, x3 = v.w * s;
    uint32_t h01 = packbf(x0, x1), h23 = packbf(x2, x3);
    uint32_t l01 = packbf(x0 - bflo(h01), x1 - bfhi(h01));
    uint32_t l23 = packbf(x2 - bflo(h23), x3 - bfhi(h23));
    ((uint2*)dh)[i4] = make_uint2(h01, h23);
    ((uint2*)dl)[i4] = make_uint2(l01, l23);
}

// ---- main attention kernel ----
__global__ void __launch_bounds__(256, 2)
attn_kernel(float* __restrict__ Og)
{
    extern __shared__ char smraw[];
    const uint32_t sb = (smem_u32(smraw) + 1023u) & ~1023u;

    const int tid = threadIdx.x, lane = tid & 31, w = tid >> 5;
    const int b = blockIdx.z, h = blockIdx.y, q0 = blockIdx.x * BQ;

    // per-lane ldmatrix constants
    const uint32_t rowK = lane & 7;
    const uint32_t selK = ((lane >> 3) & 1) * 16;
    const uint32_t rA   = 16 * w + (lane & 7) + ((lane >> 3) & 1) * 8;
    const uint32_t cA   = ((uint32_t)lane >> 4) * 16;
    const uint32_t rowV = lane & 15;

    // ---- prologue: Q chunks (16/thread) + tile0 as group0; tile1 as group1 ----
#pragma unroll
    for (int c = 0; c < 16; c++) {
        uint32_t id = c * 256 + tid;               // 0..4095
        uint32_t half = id >> 11, r = (id >> 3) & 127, c16 = id & 7;
        const __nv_bfloat16* src =
            (half ? g_Ql : g_Qh) + (((size_t)b * Lv + q0 + r) * Hv + h) * Ev + c16 * 8;
        cpa16(sb + QOFF + half * 16384 + swz(r * 128 + c16 * 16), src);
    }
    auto issue = [&](int t, uint32_t stage) {
#pragma unroll
        for (int c = 0; c < 8; c++) {
            uint32_t id = c * 256 + tid;           // 0..2047
            uint32_t half = id >> 9;               // 0:KH 1:KL 2:VH 3:VL
            uint32_t r = (id >> 3) & 63, c16 = id & 7;
            const __nv_bfloat16* base =
                half == 0 ? g_Kh : half == 1 ? g_Kl : half == 2 ? g_Vh : g_Vl;
            const __nv_bfloat16* src =
                base + (((size_t)b * Sv + t * BS + r) * Hv + h) * Ev + c16 * 8;
            cpa16(sb + stage + half * 8192 + swz(r * 128 + c16 * 16), src);
        }
    };
    issue(0, 0);
    cp_commit();           // group0 = Q + tile0
    issue(1, STAGE_SZ);
    cp_commit();           // group1 = tile1

    float Oacc[32];
#pragma unroll
    for (int i = 0; i < 32; i++) Oacc[i] = 0.0f;
    float m0 = -CUDART_INF_F, m1 = -CUDART_INF_F, l0 = 0.0f, l1 = 0.0f;

    for (int t = 0; t < NT; t++) {
        if (t == NT - 1) cp_wait<0>(); else cp_wait<1>();
        __syncthreads();
        const uint32_t stg = sb + (uint32_t)(t & 1) * STAGE_SZ;
        const uint32_t kh = stg, kl = stg + 8192, vh = stg + 16384, vl = stg + 24576;

        // ---- QK^T: S(16x64 per warp) = Qh*Kh + Ql*Kh + Qh*Kl ----
        float sc[32];
#pragma unroll
        for (int i = 0; i < 32; i++) sc[i] = 0.0f;
#pragma unroll
        for (int ks = 0; ks < 4; ks++) {
            uint32_t aH[4], aL[4];
            const uint32_t qa = sb + QOFF + swz(rA * 128 + ks * 32 + cA);
            ldsm_x4(qa, aH);
            ldsm_x4(qa + 16384, aL);
            const uint32_t kboff = swz(rowK * 128 + ks * 32 + selK);
#pragma unroll
            for (int j = 0; j < 8; j++) {
                uint32_t bh[2], bl[2];
                ldsm_x2(kh + j * 1024 + kboff, bh);
                ldsm_x2(kl + j * 1024 + kboff, bl);
                mma16816(sc + 4 * j, aH, bh);
                mma16816(sc + 4 * j, aL, bh);
                mma16816(sc + 4 * j, aH, bl);
            }
        }

        // ---- online softmax (rows g and g+8; quad = lanes tig 0..3) ----
        float mx0 = -CUDART_INF_F, mx1 = -CUDART_INF_F;
#pragma unroll
        for (int j = 0; j < 8; j++) {
            mx0 = fmaxf(mx0, fmaxf(sc[4 * j], sc[4 * j + 1]));
            mx1 = fmaxf(mx1, fmaxf(sc[4 * j + 2], sc[4 * j + 3]));
        }
#pragma unroll
        for (int d = 1; d < 4; d <<= 1) {
            mx0 = fmaxf(mx0, __shfl_xor_sync(0xffffffffu, mx0, d));
            mx1 = fmaxf(mx1, __shfl_xor_sync(0xffffffffu, mx1, d));
        }
        const float mn0 = fmaxf(m0, mx0), mn1 = fmaxf(m1, mx1);
        const float al0 = __expf(m0 - mn0), al1 = __expf(m1 - mn1);
        m0 = mn0; m1 = mn1;
        float s0 = 0.0f, s1 = 0.0f;
#pragma unroll
        for (int j = 0; j < 8; j++) {
            sc[4 * j]     = __expf(sc[4 * j]     - mn0);
            sc[4 * j + 1] = __expf(sc[4 * j + 1] - mn0);
            s0 += sc[4 * j] + sc[4 * j + 1];
            sc[4 * j + 2] = __expf(sc[4 * j + 2] - mn1);
            sc[4 * j + 3] = __expf(sc[4 * j + 3] - mn1);
            s1 += sc[4 * j + 2] + sc[4 * j + 3];
        }
#pragma unroll
        for (int d = 1; d < 4; d <<= 1) {
            s0 += __shfl_xor_sync(0xffffffffu, s0, d);
            s1 += __shfl_xor_sync(0xffffffffu, s1, d);
        }
        l0 = l0 * al0 + s0;
        l1 = l1 * al1 + s1;
#pragma unroll
        for (int j = 0; j < 8; j++) {
            Oacc[4 * j]     *= al0;
            Oacc[4 * j + 1] *= al0;
            Oacc[4 * j + 2] *= al1;
            Oacc[4 * j + 3] *= al1;
        }

        // ---- PV: O += Ph*Vh + Pl*Vh + Ph*Vl  (P from C-layout regs) ----
#pragma unroll
        for (int ks = 0; ks < 4; ks++) {
            uint32_t pH[4], pL[4];
#pragma unroll
            for (int u = 0; u < 4; u++) {
                float x0 = sc[8 * ks + 2 * u], x1 = sc[8 * ks + 2 * u + 1];
                uint32_t hp = packbf(x0, x1);
                pH[u] = hp;
                pL[u] = packbf(x0 - bflo(hp), x1 - bfhi(hp));
            }
#pragma unroll
            for (int j = 0; j < 8; j++) {
                uint32_t bh[2], bl[2];
                const uint32_t va = swz((16 * ks + rowV) * 128 + j * 16);
                ldsm_x2t(vh + va, bh);
                ldsm_x2t(vl + va, bl);
                mma16816(Oacc + 4 * j, pH, bh);
                mma16816(Oacc + 4 * j, pL, bh);
                mma16816(Oacc + 4 * j, pH, bl);
            }
        }

        __syncthreads();  // all warps done with stage (t&1)
        if (t + 2 < NT) {
            issue(t + 2, (uint32_t)(t & 1) * STAGE_SZ);
            cp_commit();
        }
    }

    // ---- epilogue ----
    const float inv0 = 1.0f / l0, inv1 = 1.0f / l1;
    const int r0 = q0 + 16 * w + (lane >> 2);
    const size_t base0 = (((size_t)b * Lv + r0) * Hv + h) * Dv;
    const size_t base1 = base0 + (size_t)8 * Hv * Dv;
#pragma unroll
    for (int j = 0; j < 8; j++) {
        const int col = 8 * j + 2 * (lane & 3);
        float2 o0 = make_float2(Oacc[4 * j] * inv0, Oacc[4 * j + 1] * inv0);
        float2 o1 = make_float2(Oacc[4 * j + 2] * inv1, Oacc[4 * j + 3] * inv1);
        *reinterpret_cast<float2*>(Og + base0 + col) = o0;
        *reinterpret_cast<float2*>(Og + base1 + col) = o1;
    }
}

}  // namespace

extern "C" void kernel_launch(void* const* d_in, const int* in_sizes, int n_in,
                              void* d_out, int out_size)
{
    const float* Q = (const float*)d_in[0];
    const float* K = (const float*)d_in[1];
    const float* V = (const float*)d_in[2];
    float* O = (float*)d_out;

    // split/scale preprocess: 4M float4-quads per tensor / 256 = 4096 blocks
    pre_kernel<<<dim3((unsigned)(NELEM / 4 / 256), 3, 1), 256>>>(Q, K, V);

    cudaFuncSetAttribute(attn_kernel,
                         cudaFuncAttributeMaxDynamicSharedMemorySize,
                         (int)SMEM_TOTAL);
    attn_kernel<<<dim3(Lv / BQ, Hv, Bv), 256, SMEM_TOTAL>>>(O);
}